// round 1
// baseline (speedup 1.0000x reference)
#include <cuda_runtime.h>
#include <stdint.h>

#define FD 128        // feature dim
#define MAXN 100000   // nodes

// Scratch (device globals — no allocation allowed in kernel_launch)
__device__ float g_deg [MAXN];
__device__ float g_dinv[MAXN];
__device__ float g_bufA[(size_t)MAXN * FD];
__device__ float g_bufB[(size_t)MAXN * FD];
__device__ float g_bufT[(size_t)MAXN * FD];

// ---------------------------------------------------------------------------
// Degree / normalization precompute
// ---------------------------------------------------------------------------
__global__ void k_deg_init(int n) {
    int i = blockIdx.x * blockDim.x + threadIdx.x;
    if (i < n) g_deg[i] = 2.0f;   // improved=True self-loop weight
}

__global__ void k_deg_count(const int* __restrict__ dst, int e) {
    int i = blockIdx.x * blockDim.x + threadIdx.x;
    if (i < e) atomicAdd(&g_deg[dst[i]], 1.0f);
}

__global__ void k_dinv(int n) {
    int i = blockIdx.x * blockDim.x + threadIdx.x;
    if (i < n) g_dinv[i] = rsqrtf(g_deg[i]);   // deg >= 2 always
}

// ---------------------------------------------------------------------------
// GEMM: C[n,128] = A[n,128] @ W[128,128]   (W row-major [k][c])
// Block: 256 threads, tile 128 rows x 128 cols, k-steps of 16.
// Each thread: 8x8 microtile.
// ---------------------------------------------------------------------------
__global__ void __launch_bounds__(256) k_gemm(const float* __restrict__ A,
                                              const float* __restrict__ W,
                                              float* __restrict__ C, int n) {
    __shared__ float sA[16][128];   // [k][row]
    __shared__ float sW[16][128];   // [k][col]

    const int tid  = threadIdx.x;
    const int row0 = blockIdx.x * 128;
    const int tr   = (tid >> 4) << 3;   // 0..120 step 8 (row offset in tile)
    const int tc   = (tid & 15) << 3;   // 0..120 step 8 (col offset in tile)

    // loader indices
    const int lr = tid >> 1;            // 0..127  (A row in tile)
    const int lk = (tid & 1) << 3;      // 0 or 8  (A k offset)
    const int wk = tid >> 4;            // 0..15   (W k row in tile)
    const int wc = (tid & 15) << 3;     // 0..120  (W col)

    float acc[8][8];
#pragma unroll
    for (int i = 0; i < 8; i++)
#pragma unroll
        for (int j = 0; j < 8; j++) acc[i][j] = 0.0f;

    for (int k0 = 0; k0 < FD; k0 += 16) {
        // ---- load A tile (128 rows x 16 k), transposed into sA[k][row]
        const int grow = row0 + lr;
        float4 a0, a1;
        if (grow < n) {
            const float4* ap = (const float4*)(A + (size_t)grow * FD + k0 + lk);
            a0 = ap[0];
            a1 = ap[1];
        } else {
            a0 = make_float4(0.f, 0.f, 0.f, 0.f);
            a1 = a0;
        }
        sA[lk + 0][lr] = a0.x; sA[lk + 1][lr] = a0.y;
        sA[lk + 2][lr] = a0.z; sA[lk + 3][lr] = a0.w;
        sA[lk + 4][lr] = a1.x; sA[lk + 5][lr] = a1.y;
        sA[lk + 6][lr] = a1.z; sA[lk + 7][lr] = a1.w;

        // ---- load W tile (16 k x 128 cols) straight
        const float4* wp = (const float4*)(W + (size_t)(k0 + wk) * FD + wc);
        *(float4*)&sW[wk][wc]     = wp[0];
        *(float4*)&sW[wk][wc + 4] = wp[1];

        __syncthreads();

#pragma unroll
        for (int kk = 0; kk < 16; kk++) {
            float4 x0 = *(const float4*)&sA[kk][tr];
            float4 x1 = *(const float4*)&sA[kk][tr + 4];
            float4 y0 = *(const float4*)&sW[kk][tc];
            float4 y1 = *(const float4*)&sW[kk][tc + 4];
            float av[8] = {x0.x, x0.y, x0.z, x0.w, x1.x, x1.y, x1.z, x1.w};
            float bv[8] = {y0.x, y0.y, y0.z, y0.w, y1.x, y1.y, y1.z, y1.w};
#pragma unroll
            for (int i = 0; i < 8; i++)
#pragma unroll
                for (int j = 0; j < 8; j++)
                    acc[i][j] = fmaf(av[i], bv[j], acc[i][j]);
        }
        __syncthreads();
    }

#pragma unroll
    for (int i = 0; i < 8; i++) {
        const int grow = row0 + tr + i;
        if (grow < n) {
            float4 o0 = make_float4(acc[i][0], acc[i][1], acc[i][2], acc[i][3]);
            float4 o1 = make_float4(acc[i][4], acc[i][5], acc[i][6], acc[i][7]);
            float* cp = C + (size_t)grow * FD + tc;
            *(float4*)(cp)     = o0;
            *(float4*)(cp + 4) = o1;
        }
    }
}

// ---------------------------------------------------------------------------
// Init output with bias + self-loop term:
//   out[i][d] = b[d] + 2*dinv[i]^2 * T[i][d]
// One thread per float4.
// ---------------------------------------------------------------------------
__global__ void __launch_bounds__(256) k_selfinit(const float* __restrict__ T,
                                                  const float* __restrict__ b,
                                                  float* __restrict__ out, int n) {
    int idx = blockIdx.x * blockDim.x + threadIdx.x;   // float4 index
    int total = n * (FD / 4);
    if (idx >= total) return;
    int node = idx >> 5;              // FD/4 = 32 float4 per node
    int c4   = (idx & 31) << 2;
    float dv = g_dinv[node];
    float w  = 2.0f * dv * dv;
    float4 t  = *(const float4*)(T + (size_t)node * FD + c4);
    float4 bb = *(const float4*)(b + c4);
    float4 o  = make_float4(fmaf(w, t.x, bb.x), fmaf(w, t.y, bb.y),
                            fmaf(w, t.z, bb.z), fmaf(w, t.w, bb.w));
    *(float4*)(out + (size_t)node * FD + c4) = o;
}

// ---------------------------------------------------------------------------
// Edge aggregation: one warp per edge.
//   out[dst] += dinv[src]*dinv[dst] * T[src]
// Lane l handles float4 at column l*4. Vectorized global reduction.
// ---------------------------------------------------------------------------
__global__ void __launch_bounds__(256) k_edges(const int* __restrict__ src,
                                               const int* __restrict__ dst,
                                               const float* __restrict__ T,
                                               float* __restrict__ out, int e) {
    int gw = blockIdx.x * (blockDim.x >> 5) + (threadIdx.x >> 5);
    if (gw >= e) return;
    int lane = threadIdx.x & 31;
    int s = __ldg(src + gw);
    int d = __ldg(dst + gw);
    float w = g_dinv[s] * g_dinv[d];
    float4 v = *(const float4*)(T + (size_t)s * FD + (lane << 2));
    float* p = out + (size_t)d * FD + (lane << 2);
    asm volatile("red.global.add.v4.f32 [%0], {%1, %2, %3, %4};"
                 :: "l"(p), "f"(w * v.x), "f"(w * v.y), "f"(w * v.z), "f"(w * v.w)
                 : "memory");
}

// ---------------------------------------------------------------------------
// Launcher
// ---------------------------------------------------------------------------
static void run_conv(const float* hin, const float* W, const float* b,
                     float* hout, float* T,
                     const int* src, const int* dst, int n, int e) {
    k_gemm<<<(n + 127) / 128, 256>>>(hin, W, T, n);
    k_selfinit<<<(n * (FD / 4) + 255) / 256, 256>>>(T, b, hout, n);
    k_edges<<<(e + 7) / 8, 256>>>(src, dst, T, hout, e);
}

extern "C" void kernel_launch(void* const* d_in, const int* in_sizes, int n_in,
                              void* d_out, int out_size) {
    const float* x  = (const float*)d_in[0];
    const int*   ei = (const int*)  d_in[1];
    const float* W1 = (const float*)d_in[2];
    const float* b1 = (const float*)d_in[3];
    const float* W2 = (const float*)d_in[4];
    const float* b2 = (const float*)d_in[5];
    float* out = (float*)d_out;

    const int n = in_sizes[0] / FD;
    const int e = in_sizes[1] / 2;
    const int* src = ei;        // edge_index[0]
    const int* dst = ei + e;    // edge_index[1]

    float *bufA, *bufB, *bufT;
    cudaGetSymbolAddress((void**)&bufA, g_bufA);
    cudaGetSymbolAddress((void**)&bufB, g_bufB);
    cudaGetSymbolAddress((void**)&bufT, g_bufT);

    // degree + normalization
    k_deg_init <<<(n + 255) / 256, 256>>>(n);
    k_deg_count<<<(e + 255) / 256, 256>>>(dst, e);
    k_dinv     <<<(n + 255) / 256, 256>>>(n);

    // conv1 + conv2 x4
    run_conv(x,    W1, b1, bufA, bufT, src, dst, n, e);
    run_conv(bufA, W2, b2, bufB, bufT, src, dst, n, e);
    run_conv(bufB, W2, b2, bufA, bufT, src, dst, n, e);
    run_conv(bufA, W2, b2, bufB, bufT, src, dst, n, e);
    run_conv(bufB, W2, b2, out,  bufT, src, dst, n, e);
}

// round 2
// speedup vs baseline: 1.7409x; 1.7409x over previous
#include <cuda_runtime.h>
#include <stdint.h>

#define FD   128        // feature dim
#define MAXN 100000     // nodes
#define MAXE 1664000    // edges (1.6M + slack)
#define SCAN_T 1024

// Scratch (device globals — no allocation allowed in kernel_launch)
__device__ float g_dinv[MAXN];
__device__ int   g_cnt  [MAXN];
__device__ int   g_rowptr[MAXN + 1];
__device__ int   g_fill [MAXN];
__device__ int   g_csrc [MAXE];
__device__ float g_bufA[(size_t)MAXN * FD];
__device__ float g_bufB[(size_t)MAXN * FD];
__device__ float g_bufT[(size_t)MAXN * FD];

// ---------------------------------------------------------------------------
// Degree / normalization / CSR build
// ---------------------------------------------------------------------------
__global__ void k_cnt_init(int n) {
    int i = blockIdx.x * blockDim.x + threadIdx.x;
    if (i < n) g_cnt[i] = 0;
}

__global__ void k_deg_count(const int* __restrict__ dst, int e) {
    int i = blockIdx.x * blockDim.x + threadIdx.x;
    if (i < e) atomicAdd(&g_cnt[dst[i]], 1);
}

__global__ void k_dinv(int n) {
    int i = blockIdx.x * blockDim.x + threadIdx.x;
    if (i < n) g_dinv[i] = rsqrtf(2.0f + (float)g_cnt[i]);  // improved self-loop = 2
}

// Single-block exclusive scan over g_cnt -> g_rowptr / g_fill
__global__ void __launch_bounds__(SCAN_T) k_scan(int n) {
    __shared__ int sums[SCAN_T];
    int t = threadIdx.x;
    int C = (n + SCAN_T - 1) / SCAN_T;
    int lo = t * C;
    int hi = lo + C; if (hi > n) hi = n;
    int s = 0;
    for (int i = lo; i < hi; i++) s += g_cnt[i];
    sums[t] = s;
    __syncthreads();
    // Hillis-Steele inclusive scan
    for (int off = 1; off < SCAN_T; off <<= 1) {
        int v = (t >= off) ? sums[t - off] : 0;
        __syncthreads();
        sums[t] += v;
        __syncthreads();
    }
    int pre = (t == 0) ? 0 : sums[t - 1];
    for (int i = lo; i < hi; i++) {
        g_rowptr[i] = pre;
        g_fill[i]   = pre;
        pre += g_cnt[i];
    }
    if (t == SCAN_T - 1) g_rowptr[n] = pre;
}

__global__ void k_scatter(const int* __restrict__ src, const int* __restrict__ dst, int e) {
    int i = blockIdx.x * blockDim.x + threadIdx.x;
    if (i < e) {
        int d = dst[i];
        int pos = atomicAdd(&g_fill[d], 1);
        g_csrc[pos] = src[i];
    }
}

// ---------------------------------------------------------------------------
// GEMM: T[n,128] = dinv[row] * (A[n,128] @ W[128,128])
// Block: 256 threads, tile 128x128, k-steps of 16, 8x8 microtile per thread.
// ---------------------------------------------------------------------------
__global__ void __launch_bounds__(256) k_gemm(const float* __restrict__ A,
                                              const float* __restrict__ W,
                                              float* __restrict__ T, int n) {
    __shared__ float sA[16][128];   // [k][row]
    __shared__ float sW[16][128];   // [k][col]

    const int tid  = threadIdx.x;
    const int row0 = blockIdx.x * 128;
    const int tr   = (tid >> 4) << 3;
    const int tc   = (tid & 15) << 3;

    const int lr = tid >> 1;
    const int lk = (tid & 1) << 3;
    const int wk = tid >> 4;
    const int wc = (tid & 15) << 3;

    float acc[8][8];
#pragma unroll
    for (int i = 0; i < 8; i++)
#pragma unroll
        for (int j = 0; j < 8; j++) acc[i][j] = 0.0f;

    for (int k0 = 0; k0 < FD; k0 += 16) {
        const int grow = row0 + lr;
        float4 a0, a1;
        if (grow < n) {
            const float4* ap = (const float4*)(A + (size_t)grow * FD + k0 + lk);
            a0 = ap[0];
            a1 = ap[1];
        } else {
            a0 = make_float4(0.f, 0.f, 0.f, 0.f);
            a1 = a0;
        }
        sA[lk + 0][lr] = a0.x; sA[lk + 1][lr] = a0.y;
        sA[lk + 2][lr] = a0.z; sA[lk + 3][lr] = a0.w;
        sA[lk + 4][lr] = a1.x; sA[lk + 5][lr] = a1.y;
        sA[lk + 6][lr] = a1.z; sA[lk + 7][lr] = a1.w;

        const float4* wp = (const float4*)(W + (size_t)(k0 + wk) * FD + wc);
        *(float4*)&sW[wk][wc]     = wp[0];
        *(float4*)&sW[wk][wc + 4] = wp[1];

        __syncthreads();

#pragma unroll
        for (int kk = 0; kk < 16; kk++) {
            float4 x0 = *(const float4*)&sA[kk][tr];
            float4 x1 = *(const float4*)&sA[kk][tr + 4];
            float4 y0 = *(const float4*)&sW[kk][tc];
            float4 y1 = *(const float4*)&sW[kk][tc + 4];
            float av[8] = {x0.x, x0.y, x0.z, x0.w, x1.x, x1.y, x1.z, x1.w};
            float bv[8] = {y0.x, y0.y, y0.z, y0.w, y1.x, y1.y, y1.z, y1.w};
#pragma unroll
            for (int i = 0; i < 8; i++)
#pragma unroll
                for (int j = 0; j < 8; j++)
                    acc[i][j] = fmaf(av[i], bv[j], acc[i][j]);
        }
        __syncthreads();
    }

#pragma unroll
    for (int i = 0; i < 8; i++) {
        const int grow = row0 + tr + i;
        if (grow < n) {
            float dv = g_dinv[grow];
            float4 o0 = make_float4(dv * acc[i][0], dv * acc[i][1],
                                    dv * acc[i][2], dv * acc[i][3]);
            float4 o1 = make_float4(dv * acc[i][4], dv * acc[i][5],
                                    dv * acc[i][6], dv * acc[i][7]);
            float* cp = T + (size_t)grow * FD + tc;
            *(float4*)(cp)     = o0;
            *(float4*)(cp + 4) = o1;
        }
    }
}

// ---------------------------------------------------------------------------
// Gather aggregation: one warp per node.
//   out[d] = dinv[d] * ( sum_{s in N(d)} T[s] + 2*T[d] ) + b
// Lane l handles float4 at column l*4. No atomics; coalesced writes.
// ---------------------------------------------------------------------------
__global__ void __launch_bounds__(256) k_agg(const float* __restrict__ T,
                                             const float* __restrict__ b,
                                             float* __restrict__ out, int n) {
    int node = blockIdx.x * (blockDim.x >> 5) + (threadIdx.x >> 5);
    if (node >= n) return;
    const int lane = threadIdx.x & 31;
    const int c = lane << 2;

    const int beg = g_rowptr[node];
    const int end = g_rowptr[node + 1];

    float4 self = *(const float4*)(T + (size_t)node * FD + c);
    float ax = 2.0f * self.x, ay = 2.0f * self.y;
    float az = 2.0f * self.z, aw = 2.0f * self.w;

    int j = beg;
    for (; j + 3 < end; j += 4) {
        int s0 = __ldg(g_csrc + j);
        int s1 = __ldg(g_csrc + j + 1);
        int s2 = __ldg(g_csrc + j + 2);
        int s3 = __ldg(g_csrc + j + 3);
        float4 v0 = *(const float4*)(T + (size_t)s0 * FD + c);
        float4 v1 = *(const float4*)(T + (size_t)s1 * FD + c);
        float4 v2 = *(const float4*)(T + (size_t)s2 * FD + c);
        float4 v3 = *(const float4*)(T + (size_t)s3 * FD + c);
        ax += v0.x + v1.x + v2.x + v3.x;
        ay += v0.y + v1.y + v2.y + v3.y;
        az += v0.z + v1.z + v2.z + v3.z;
        aw += v0.w + v1.w + v2.w + v3.w;
    }
    for (; j < end; j++) {
        int s = __ldg(g_csrc + j);
        float4 v = *(const float4*)(T + (size_t)s * FD + c);
        ax += v.x; ay += v.y; az += v.z; aw += v.w;
    }

    float dv = g_dinv[node];
    float4 bb = *(const float4*)(b + c);
    float4 o = make_float4(fmaf(dv, ax, bb.x), fmaf(dv, ay, bb.y),
                           fmaf(dv, az, bb.z), fmaf(dv, aw, bb.w));
    *(float4*)(out + (size_t)node * FD + c) = o;
}

// ---------------------------------------------------------------------------
// Launcher
// ---------------------------------------------------------------------------
static void run_conv(const float* hin, const float* W, const float* b,
                     float* hout, float* T, int n) {
    k_gemm<<<(n + 127) / 128, 256>>>(hin, W, T, n);
    k_agg <<<(n + 7) / 8, 256>>>(T, b, hout, n);
}

extern "C" void kernel_launch(void* const* d_in, const int* in_sizes, int n_in,
                              void* d_out, int out_size) {
    const float* x  = (const float*)d_in[0];
    const int*   ei = (const int*)  d_in[1];
    const float* W1 = (const float*)d_in[2];
    const float* b1 = (const float*)d_in[3];
    const float* W2 = (const float*)d_in[4];
    const float* b2 = (const float*)d_in[5];
    float* out = (float*)d_out;

    const int n = in_sizes[0] / FD;
    const int e = in_sizes[1] / 2;
    const int* src = ei;        // edge_index[0]
    const int* dst = ei + e;    // edge_index[1]

    float *bufA, *bufB, *bufT;
    cudaGetSymbolAddress((void**)&bufA, g_bufA);
    cudaGetSymbolAddress((void**)&bufB, g_bufB);
    cudaGetSymbolAddress((void**)&bufT, g_bufT);

    // degree + normalization + CSR build
    k_cnt_init <<<(n + 255) / 256, 256>>>(n);
    k_deg_count<<<(e + 255) / 256, 256>>>(dst, e);
    k_dinv     <<<(n + 255) / 256, 256>>>(n);
    k_scan     <<<1, SCAN_T>>>(n);
    k_scatter  <<<(e + 255) / 256, 256>>>(src, dst, e);

    // conv1 + conv2 x4
    run_conv(x,    W1, b1, bufA, bufT, n);
    run_conv(bufA, W2, b2, bufB, bufT, n);
    run_conv(bufB, W2, b2, bufA, bufT, n);
    run_conv(bufA, W2, b2, bufB, bufT, n);
    run_conv(bufB, W2, b2, out,  bufT, n);
}

// round 3
// speedup vs baseline: 1.8669x; 1.0724x over previous
#include <cuda_runtime.h>
#include <stdint.h>

#define FD   128        // feature dim
#define MAXN 100000     // nodes
#define MAXE 1664000    // edges (1.6M + slack)
#define CHUNK 1024      // elements per scan block

// Scratch (device globals — no allocation allowed in kernel_launch)
__device__ float g_dinv[MAXN];
__device__ int   g_cnt  [MAXN];
__device__ int   g_rowptr[MAXN + 1];
__device__ int   g_fill [MAXN];
__device__ int   g_csrc [MAXE];
__device__ int   g_bsum [256];
__device__ int   g_boff [256];
__device__ float g_bufA[(size_t)MAXN * FD];
__device__ float g_bufB[(size_t)MAXN * FD];
__device__ float g_bufT[(size_t)MAXN * FD];

#define FMA2(d, a, b) asm("fma.rn.f32x2 %0, %1, %2, %3;" \
                          : "=l"(d) : "l"(a), "l"(b), "l"(d))

// ---------------------------------------------------------------------------
// Degree / normalization
// ---------------------------------------------------------------------------
__global__ void k_cnt_init(int n) {
    int i = blockIdx.x * blockDim.x + threadIdx.x;
    if (i < n) g_cnt[i] = 0;
}

__global__ void k_deg_count(const int* __restrict__ dst, int e) {
    int i = blockIdx.x * blockDim.x + threadIdx.x;
    if (i < e) atomicAdd(&g_cnt[dst[i]], 1);
}

__global__ void k_dinv(int n) {
    int i = blockIdx.x * blockDim.x + threadIdx.x;
    if (i < n) g_dinv[i] = rsqrtf(2.0f + (float)g_cnt[i]);  // improved self-loop = 2
}

// ---------------------------------------------------------------------------
// 3-pass parallel exclusive scan of g_cnt -> g_rowptr / g_fill
// ---------------------------------------------------------------------------
// Pass 1: per-block (1024 elems) reduction
__global__ void __launch_bounds__(256) k_scan1(int n) {
    const int t = threadIdx.x;
    const int base = blockIdx.x * CHUNK + t * 4;
    int s = 0;
#pragma unroll
    for (int m = 0; m < 4; m++) {
        int i = base + m;
        if (i < n) s += g_cnt[i];
    }
#pragma unroll
    for (int o = 16; o > 0; o >>= 1) s += __shfl_down_sync(0xffffffffu, s, o);
    __shared__ int ws[8];
    if ((t & 31) == 0) ws[t >> 5] = s;
    __syncthreads();
    if (t < 8) {
        int v = ws[t];
#pragma unroll
        for (int o = 4; o > 0; o >>= 1) v += __shfl_down_sync(0xffu, v, o);
        if (t == 0) g_bsum[blockIdx.x] = v;
    }
}

// Pass 2: single block scans up to 256 block sums
__global__ void __launch_bounds__(256) k_scan2(int nb, int n) {
    __shared__ int sh[256];
    int t = threadIdx.x;
    int v = (t < nb) ? g_bsum[t] : 0;
    sh[t] = v;
    __syncthreads();
#pragma unroll
    for (int o = 1; o < 256; o <<= 1) {
        int u = (t >= o) ? sh[t - o] : 0;
        __syncthreads();
        sh[t] += u;
        __syncthreads();
    }
    g_boff[t] = sh[t] - v;           // exclusive block offset
    if (t == nb - 1) g_rowptr[n] = sh[t];  // total
}

// Pass 3: block-local exclusive scan + apply block offset
__global__ void __launch_bounds__(256) k_scan3(int n) {
    const int t = threadIdx.x;
    const int lane = t & 31;
    const int warp = t >> 5;
    const int base = blockIdx.x * CHUNK + t * 4;

    int c[4];
    int s = 0;
#pragma unroll
    for (int m = 0; m < 4; m++) {
        int i = base + m;
        c[m] = (i < n) ? g_cnt[i] : 0;
        s += c[m];
    }
    // warp inclusive scan of s
    int incl = s;
#pragma unroll
    for (int o = 1; o < 32; o <<= 1) {
        int u = __shfl_up_sync(0xffffffffu, incl, o);
        if (lane >= o) incl += u;
    }
    __shared__ int wtot[8];
    if (lane == 31) wtot[warp] = incl;
    __syncthreads();
    int woff = 0;
    if (warp > 0) {
#pragma unroll
        for (int w = 0; w < 7; w++)
            if (w < warp) woff += wtot[w];
    }
    int pre = g_boff[blockIdx.x] + woff + incl - s;  // exclusive prefix for elem 0
#pragma unroll
    for (int m = 0; m < 4; m++) {
        int i = base + m;
        if (i < n) {
            g_rowptr[i] = pre;
            g_fill[i]   = pre;
            pre += c[m];
        }
    }
}

__global__ void k_scatter(const int* __restrict__ src, const int* __restrict__ dst, int e) {
    int i = blockIdx.x * blockDim.x + threadIdx.x;
    if (i < e) {
        int d = dst[i];
        int pos = atomicAdd(&g_fill[d], 1);
        g_csrc[pos] = src[i];
    }
}

// ---------------------------------------------------------------------------
// GEMM: T[n,128] = dinv[row] * (A[n,128] @ W[128,128])
// 256 threads, 128x128 tile, k-steps of 16, 8x8 microtile, FFMA2 (f32x2).
// A is stored DUPLICATED in smem ({a,a} pairs) so both operands of
// fma.rn.f32x2 come straight out of LDS.128 register pairs (no pack MOVs).
// ---------------------------------------------------------------------------
__global__ void __launch_bounds__(256) k_gemm(const float* __restrict__ A,
                                              const float* __restrict__ W,
                                              float* __restrict__ T, int n) {
    __shared__ float sAd[16][256];   // [k][2*row] duplicated pairs (16KB)
    __shared__ float sW [16][128];   // [k][col]                     (8KB)

    const int tid  = threadIdx.x;
    const int row0 = blockIdx.x * 128;
    const int tr   = (tid >> 4) << 3;   // row offset in tile
    const int tc   = (tid & 15) << 3;   // col offset in tile

    const int lr = tid >> 1;            // A row in tile (0..127)
    const int lk = (tid & 1) << 3;      // A k offset (0 or 8)
    const int wk = tid >> 4;            // W k row (0..15)
    const int wc = (tid & 15) << 3;     // W col

    unsigned long long acc2[8][4];      // 8 rows x 4 col-pairs, f32x2 each
#pragma unroll
    for (int i = 0; i < 8; i++)
#pragma unroll
        for (int j = 0; j < 4; j++) acc2[i][j] = 0ull;

    for (int k0 = 0; k0 < FD; k0 += 16) {
        // ---- load A tile, store transposed + duplicated: sAd[k][2r]=sAd[k][2r+1]=a
        const int grow = row0 + lr;
        float4 a0, a1;
        if (grow < n) {
            const float4* ap = (const float4*)(A + (size_t)grow * FD + k0 + lk);
            a0 = ap[0];
            a1 = ap[1];
        } else {
            a0 = make_float4(0.f, 0.f, 0.f, 0.f);
            a1 = a0;
        }
        {
            float av[8] = {a0.x, a0.y, a0.z, a0.w, a1.x, a1.y, a1.z, a1.w};
#pragma unroll
            for (int m = 0; m < 8; m++)
                *(float2*)&sAd[lk + m][lr << 1] = make_float2(av[m], av[m]);
        }

        // ---- load W tile straight
        const float4* wp = (const float4*)(W + (size_t)(k0 + wk) * FD + wc);
        *(float4*)&sW[wk][wc]     = wp[0];
        *(float4*)&sW[wk][wc + 4] = wp[1];

        __syncthreads();

#pragma unroll
        for (int kk = 0; kk < 16; kk++) {
            const float* arow = &sAd[kk][tr << 1];
            ulonglong2 A01 = *(const ulonglong2*)(arow + 0);
            ulonglong2 A23 = *(const ulonglong2*)(arow + 4);
            ulonglong2 A45 = *(const ulonglong2*)(arow + 8);
            ulonglong2 A67 = *(const ulonglong2*)(arow + 12);
            const float* wrow = &sW[kk][tc];
            ulonglong2 B01 = *(const ulonglong2*)(wrow);
            ulonglong2 B23 = *(const ulonglong2*)(wrow + 4);

            unsigned long long aa[8] = {A01.x, A01.y, A23.x, A23.y,
                                        A45.x, A45.y, A67.x, A67.y};
            unsigned long long bp[4] = {B01.x, B01.y, B23.x, B23.y};
#pragma unroll
            for (int i = 0; i < 8; i++) {
#pragma unroll
                for (int j = 0; j < 4; j++)
                    FMA2(acc2[i][j], aa[i], bp[j]);
            }
        }
        __syncthreads();
    }

#pragma unroll
    for (int i = 0; i < 8; i++) {
        const int grow = row0 + tr + i;
        if (grow < n) {
            float dv = g_dinv[grow];
            float2 p0 = *(float2*)&acc2[i][0];
            float2 p1 = *(float2*)&acc2[i][1];
            float2 p2 = *(float2*)&acc2[i][2];
            float2 p3 = *(float2*)&acc2[i][3];
            float4 o0 = make_float4(dv * p0.x, dv * p0.y, dv * p1.x, dv * p1.y);
            float4 o1 = make_float4(dv * p2.x, dv * p2.y, dv * p3.x, dv * p3.y);
            float* cp = T + (size_t)grow * FD + tc;
            *(float4*)(cp)     = o0;
            *(float4*)(cp + 4) = o1;
        }
    }
}

// ---------------------------------------------------------------------------
// Gather aggregation: one warp per node.
//   out[d] = dinv[d] * ( sum_{s in N(d)} T[s] + 2*T[d] ) + b
// ---------------------------------------------------------------------------
__global__ void __launch_bounds__(256) k_agg(const float* __restrict__ T,
                                             const float* __restrict__ b,
                                             float* __restrict__ out, int n) {
    int node = blockIdx.x * (blockDim.x >> 5) + (threadIdx.x >> 5);
    if (node >= n) return;
    const int lane = threadIdx.x & 31;
    const int c = lane << 2;

    const int beg = g_rowptr[node];
    const int end = g_rowptr[node + 1];

    float4 self = *(const float4*)(T + (size_t)node * FD + c);
    float ax = 2.0f * self.x, ay = 2.0f * self.y;
    float az = 2.0f * self.z, aw = 2.0f * self.w;

    int j = beg;
    for (; j + 3 < end; j += 4) {
        int s0 = __ldg(g_csrc + j);
        int s1 = __ldg(g_csrc + j + 1);
        int s2 = __ldg(g_csrc + j + 2);
        int s3 = __ldg(g_csrc + j + 3);
        float4 v0 = *(const float4*)(T + (size_t)s0 * FD + c);
        float4 v1 = *(const float4*)(T + (size_t)s1 * FD + c);
        float4 v2 = *(const float4*)(T + (size_t)s2 * FD + c);
        float4 v3 = *(const float4*)(T + (size_t)s3 * FD + c);
        ax += v0.x + v1.x + v2.x + v3.x;
        ay += v0.y + v1.y + v2.y + v3.y;
        az += v0.z + v1.z + v2.z + v3.z;
        aw += v0.w + v1.w + v2.w + v3.w;
    }
    for (; j < end; j++) {
        int s = __ldg(g_csrc + j);
        float4 v = *(const float4*)(T + (size_t)s * FD + c);
        ax += v.x; ay += v.y; az += v.z; aw += v.w;
    }

    float dv = g_dinv[node];
    float4 bb = *(const float4*)(b + c);
    float4 o = make_float4(fmaf(dv, ax, bb.x), fmaf(dv, ay, bb.y),
                           fmaf(dv, az, bb.z), fmaf(dv, aw, bb.w));
    *(float4*)(out + (size_t)node * FD + c) = o;
}

// ---------------------------------------------------------------------------
// Launcher
// ---------------------------------------------------------------------------
static void run_conv(const float* hin, const float* W, const float* b,
                     float* hout, float* T, int n) {
    k_gemm<<<(n + 127) / 128, 256>>>(hin, W, T, n);
    k_agg <<<(n + 7) / 8, 256>>>(T, b, hout, n);
}

extern "C" void kernel_launch(void* const* d_in, const int* in_sizes, int n_in,
                              void* d_out, int out_size) {
    const float* x  = (const float*)d_in[0];
    const int*   ei = (const int*)  d_in[1];
    const float* W1 = (const float*)d_in[2];
    const float* b1 = (const float*)d_in[3];
    const float* W2 = (const float*)d_in[4];
    const float* b2 = (const float*)d_in[5];
    float* out = (float*)d_out;

    const int n = in_sizes[0] / FD;
    const int e = in_sizes[1] / 2;
    const int* src = ei;        // edge_index[0]
    const int* dst = ei + e;    // edge_index[1]

    float *bufA, *bufB, *bufT;
    cudaGetSymbolAddress((void**)&bufA, g_bufA);
    cudaGetSymbolAddress((void**)&bufB, g_bufB);
    cudaGetSymbolAddress((void**)&bufT, g_bufT);

    const int nb = (n + CHUNK - 1) / CHUNK;

    // degree + normalization + CSR build
    k_cnt_init <<<(n + 255) / 256, 256>>>(n);
    k_deg_count<<<(e + 255) / 256, 256>>>(dst, e);
    k_dinv     <<<(n + 255) / 256, 256>>>(n);
    k_scan1    <<<nb, 256>>>(n);
    k_scan2    <<<1, 256>>>(nb, n);
    k_scan3    <<<nb, 256>>>(n);
    k_scatter  <<<(e + 255) / 256, 256>>>(src, dst, e);

    // conv1 + conv2 x4
    run_conv(x,    W1, b1, bufA, bufT, n);
    run_conv(bufA, W2, b2, bufB, bufT, n);
    run_conv(bufB, W2, b2, bufA, bufT, n);
    run_conv(bufA, W2, b2, bufB, bufT, n);
    run_conv(bufB, W2, b2, out,  bufT, n);
}

// round 6
// speedup vs baseline: 2.6848x; 1.4381x over previous
#include <cuda_runtime.h>
#include <cuda_bf16.h>
#include <stdint.h>

#define FD   128        // feature dim
#define MAXN 100000     // nodes
#define MAXE 1664000    // edges (1.6M + slack)
#define CHUNK 1024      // elements per scan block
#define TILE_M 128
#define SROW 136        // smem tile row stride in bf16 elems (272B, conflict-free)
#define SROWB (SROW * 2)

// ---------------------------------------------------------------------------
// Scratch (device globals — no allocation allowed in kernel_launch)
// ---------------------------------------------------------------------------
__device__ float g_dinv[MAXN];
__device__ int   g_cnt  [MAXN];
__device__ int   g_rowptr[MAXN + 1];
__device__ int   g_fill [MAXN];
__device__ int   g_csrc [MAXE];
__device__ int   g_bsum [256];
__device__ int   g_boff [256];
__device__ __align__(128) float g_bufT[(size_t)(MAXN + 128) * FD];
__device__ __align__(128) __nv_bfloat16 g_hh[(size_t)(MAXN + 128) * FD];
__device__ __align__(128) __nv_bfloat16 g_hl[(size_t)(MAXN + 128) * FD];
__device__ __align__(128) __nv_bfloat16 g_W1h[FD * FD];
__device__ __align__(128) __nv_bfloat16 g_W1l[FD * FD];
__device__ __align__(128) __nv_bfloat16 g_W2h[FD * FD];
__device__ __align__(128) __nv_bfloat16 g_W2l[FD * FD];

// ---------------------------------------------------------------------------
// Degree / normalization
// ---------------------------------------------------------------------------
__global__ void k_cnt_init(int n) {
    int i = blockIdx.x * blockDim.x + threadIdx.x;
    if (i < n) g_cnt[i] = 0;
}

__global__ void k_deg_count(const int* __restrict__ dst, int e) {
    int i = blockIdx.x * blockDim.x + threadIdx.x;
    if (i < e) atomicAdd(&g_cnt[dst[i]], 1);
}

__global__ void k_dinv(int n) {
    int i = blockIdx.x * blockDim.x + threadIdx.x;
    if (i < n) g_dinv[i] = rsqrtf(2.0f + (float)g_cnt[i]);
}

// ---------------------------------------------------------------------------
// 3-pass parallel exclusive scan of g_cnt -> g_rowptr / g_fill
// ---------------------------------------------------------------------------
__global__ void __launch_bounds__(256) k_scan1(int n) {
    const int t = threadIdx.x;
    const int base = blockIdx.x * CHUNK + t * 4;
    int s = 0;
#pragma unroll
    for (int m = 0; m < 4; m++) {
        int i = base + m;
        if (i < n) s += g_cnt[i];
    }
#pragma unroll
    for (int o = 16; o > 0; o >>= 1) s += __shfl_down_sync(0xffffffffu, s, o);
    __shared__ int ws[8];
    if ((t & 31) == 0) ws[t >> 5] = s;
    __syncthreads();
    if (t < 8) {
        int v = ws[t];
#pragma unroll
        for (int o = 4; o > 0; o >>= 1) v += __shfl_down_sync(0xffu, v, o);
        if (t == 0) g_bsum[blockIdx.x] = v;
    }
}

__global__ void __launch_bounds__(256) k_scan2(int nb, int n) {
    __shared__ int sh[256];
    int t = threadIdx.x;
    int v = (t < nb) ? g_bsum[t] : 0;
    sh[t] = v;
    __syncthreads();
#pragma unroll
    for (int o = 1; o < 256; o <<= 1) {
        int u = (t >= o) ? sh[t - o] : 0;
        __syncthreads();
        sh[t] += u;
        __syncthreads();
    }
    g_boff[t] = sh[t] - v;
    if (t == nb - 1) g_rowptr[n] = sh[t];
}

__global__ void __launch_bounds__(256) k_scan3(int n) {
    const int t = threadIdx.x;
    const int lane = t & 31;
    const int warp = t >> 5;
    const int base = blockIdx.x * CHUNK + t * 4;

    int c[4];
    int s = 0;
#pragma unroll
    for (int m = 0; m < 4; m++) {
        int i = base + m;
        c[m] = (i < n) ? g_cnt[i] : 0;
        s += c[m];
    }
    int incl = s;
#pragma unroll
    for (int o = 1; o < 32; o <<= 1) {
        int u = __shfl_up_sync(0xffffffffu, incl, o);
        if (lane >= o) incl += u;
    }
    __shared__ int wtot[8];
    if (lane == 31) wtot[warp] = incl;
    __syncthreads();
    int woff = 0;
#pragma unroll
    for (int w = 0; w < 7; w++)
        if (w < warp) woff += wtot[w];
    int pre = g_boff[blockIdx.x] + woff + incl - s;
#pragma unroll
    for (int m = 0; m < 4; m++) {
        int i = base + m;
        if (i < n) {
            g_rowptr[i] = pre;
            g_fill[i]   = pre;
            pre += c[m];
        }
    }
}

__global__ void k_scatter(const int* __restrict__ src, const int* __restrict__ dst, int e) {
    int i = blockIdx.x * blockDim.x + threadIdx.x;
    if (i < e) {
        int d = dst[i];
        int pos = atomicAdd(&g_fill[d], 1);
        g_csrc[pos] = src[i];
    }
}

// ---------------------------------------------------------------------------
// Split helpers: fp32 -> bf16 hi/lo
// ---------------------------------------------------------------------------
__device__ __forceinline__ void split4(float4 v, uint2& hi, uint2& lo) {
    __nv_bfloat16 hx = __float2bfloat16_rn(v.x);
    __nv_bfloat16 hy = __float2bfloat16_rn(v.y);
    __nv_bfloat16 hz = __float2bfloat16_rn(v.z);
    __nv_bfloat16 hw = __float2bfloat16_rn(v.w);
    __nv_bfloat16 lx = __float2bfloat16_rn(v.x - __bfloat162float(hx));
    __nv_bfloat16 ly = __float2bfloat16_rn(v.y - __bfloat162float(hy));
    __nv_bfloat16 lz = __float2bfloat16_rn(v.z - __bfloat162float(hz));
    __nv_bfloat16 lw = __float2bfloat16_rn(v.w - __bfloat162float(hw));
    __nv_bfloat162 h0 = __halves2bfloat162(hx, hy), h1 = __halves2bfloat162(hz, hw);
    __nv_bfloat162 l0 = __halves2bfloat162(lx, ly), l1 = __halves2bfloat162(lz, lw);
    hi = make_uint2(*(uint32_t*)&h0, *(uint32_t*)&h1);
    lo = make_uint2(*(uint32_t*)&l0, *(uint32_t*)&l1);
}

__global__ void __launch_bounds__(256) k_split_x(const float* __restrict__ x, int total4) {
    int i = blockIdx.x * blockDim.x + threadIdx.x;   // float4 index
    if (i >= total4) return;
    float4 v = *(const float4*)(x + (size_t)i * 4);
    uint2 hi, lo;
    split4(v, hi, lo);
    *(uint2*)(g_hh + (size_t)i * 4) = hi;
    *(uint2*)(g_hl + (size_t)i * 4) = lo;
}

// W[k][n] fp32 -> Wh/Wl[n][k] bf16 (transposed: n rows, k contiguous)
__global__ void __launch_bounds__(256) k_wsplit(const float* __restrict__ W,
                                                __nv_bfloat16* __restrict__ Wh,
                                                __nv_bfloat16* __restrict__ Wl) {
    int i = blockIdx.x * blockDim.x + threadIdx.x;   // i = n*128 + k
    if (i >= FD * FD) return;
    int nn = i >> 7, kk = i & 127;
    float w = W[kk * FD + nn];
    __nv_bfloat16 h = __float2bfloat16_rn(w);
    __nv_bfloat16 l = __float2bfloat16_rn(w - __bfloat162float(h));
    Wh[i] = h;
    Wl[i] = l;
}

// ---------------------------------------------------------------------------
// HMMA GEMM: T[n,128] = dinv[row] * (A @ W), fp32 via bf16 3-term split
//   D = Ah@Wh + Ah@Wl + Al@Wh   (fp32 accumulation in registers)
// 256 threads, 128x128 tile, mma.sync.m16n8k16.bf16, ldmatrix from smem.
// ---------------------------------------------------------------------------
__device__ __forceinline__ uint32_t smem_to_u32(const void* p) {
    uint32_t a;
    asm("{ .reg .u64 t; cvta.to.shared.u64 t, %1; cvt.u32.u64 %0, t; }"
        : "=r"(a) : "l"(p));
    return a;
}

__device__ __forceinline__ void ldsm_x4(uint32_t& r0, uint32_t& r1,
                                        uint32_t& r2, uint32_t& r3, uint32_t addr) {
    asm volatile("ldmatrix.sync.aligned.m8n8.x4.shared.b16 {%0,%1,%2,%3}, [%4];"
                 : "=r"(r0), "=r"(r1), "=r"(r2), "=r"(r3) : "r"(addr));
}

// NON-transposed: W stored [n][k] (k contiguous) => B fragment pairs along k
__device__ __forceinline__ void ldsm_x2(uint32_t& r0, uint32_t& r1, uint32_t addr) {
    asm volatile("ldmatrix.sync.aligned.m8n8.x2.shared.b16 {%0,%1}, [%2];"
                 : "=r"(r0), "=r"(r1) : "r"(addr));
}

__device__ __forceinline__ void mma16816(float* c, uint32_t a0, uint32_t a1,
                                         uint32_t a2, uint32_t a3,
                                         uint32_t b0, uint32_t b1) {
    asm volatile(
        "mma.sync.aligned.m16n8k16.row.col.f32.bf16.bf16.f32 "
        "{%0,%1,%2,%3}, {%4,%5,%6,%7}, {%8,%9}, {%0,%1,%2,%3};"
        : "+f"(c[0]), "+f"(c[1]), "+f"(c[2]), "+f"(c[3])
        : "r"(a0), "r"(a1), "r"(a2), "r"(a3), "r"(b0), "r"(b1));
}

// Copy a 128x128 bf16 tile (row-major, contiguous) to smem with SROW stride.
__device__ __forceinline__ void load_tile(char* dst, const __nv_bfloat16* g,
                                          int valid_rows) {
    const uint4* gp = (const uint4*)g;   // 2048 uint4, 16 per row
    const int tid = threadIdx.x;
#pragma unroll
    for (int i = 0; i < 8; i++) {
        int gi = tid + i * 256;
        int r  = gi >> 4;
        int ch = gi & 15;
        uint4 v = (r < valid_rows) ? gp[gi] : make_uint4(0u, 0u, 0u, 0u);
        *(uint4*)(dst + r * SROWB + ch * 16) = v;
    }
}

#define SM_AH 0
#define SM_AL (128 * SROWB)
#define SM_WH (2 * 128 * SROWB)
#define SM_WL (3 * 128 * SROWB)
#define SM_TOTAL (4 * 128 * SROWB)

__global__ void __launch_bounds__(256)
k_gemm_mma(const __nv_bfloat16* __restrict__ Ah,
           const __nv_bfloat16* __restrict__ Al,
           const __nv_bfloat16* __restrict__ Wh,
           const __nv_bfloat16* __restrict__ Wl,
           float* __restrict__ T, int n) {
    extern __shared__ char smem[];
    const int tid  = threadIdx.x;
    const int lane = tid & 31;
    const int wr0  = (tid >> 5) << 4;    // warp row offset: 0..112
    const int row0 = blockIdx.x * TILE_M;
    const int valid = min(TILE_M, n - row0);

    load_tile(smem + SM_AH, Ah + (size_t)row0 * FD, valid);
    load_tile(smem + SM_AL, Al + (size_t)row0 * FD, valid);
    load_tile(smem + SM_WH, Wh, 128);
    load_tile(smem + SM_WL, Wl, 128);
    __syncthreads();

    const uint32_t sb = smem_to_u32(smem);
    // A frag address: row = wr0 + (lane&15), col bytes = ((lane>>4)<<3)*2
    const uint32_t aoff = sb + (uint32_t)(wr0 + (lane & 15)) * SROWB
                        + (uint32_t)((lane >> 4) << 4);
    // B frag address (non-trans x2): lanes 0-7 -> n rows 0-7 (k0-7),
    // lanes 8-15 -> same n rows, k8-15 (+16 bytes)
    const uint32_t boff = sb + (uint32_t)(lane & 7) * SROWB
                        + (uint32_t)(((lane >> 3) & 1) << 4);

    float acc[16][4];
#pragma unroll
    for (int t = 0; t < 16; t++)
#pragma unroll
        for (int j = 0; j < 4; j++) acc[t][j] = 0.0f;

#pragma unroll
    for (int term = 0; term < 3; term++) {
        const uint32_t aBase = aoff + ((term == 2) ? SM_AL : SM_AH);
        const uint32_t bBase = boff + ((term == 1) ? SM_WL : SM_WH);
#pragma unroll
        for (int k0 = 0; k0 < 128; k0 += 16) {
            uint32_t a0, a1, a2, a3;
            ldsm_x4(a0, a1, a2, a3, aBase + k0 * 2);
#pragma unroll
            for (int t = 0; t < 16; t++) {
                uint32_t b0, b1;
                ldsm_x2(b0, b1, bBase + (uint32_t)t * 8 * SROWB + k0 * 2);
                mma16816(acc[t], a0, a1, a2, a3, b0, b1);
            }
        }
    }

    // epilogue: scale by dinv[row], store fp32
    const int r0g = row0 + wr0 + (lane >> 2);
    const int r1g = r0g + 8;
    const float dv0 = (r0g < n) ? g_dinv[r0g] : 0.0f;
    const float dv1 = (r1g < n) ? g_dinv[r1g] : 0.0f;
    const int cbase = (lane & 3) << 1;
#pragma unroll
    for (int t = 0; t < 16; t++) {
        const int col = t * 8 + cbase;
        if (r0g < n)
            *(float2*)(T + (size_t)r0g * FD + col) =
                make_float2(dv0 * acc[t][0], dv0 * acc[t][1]);
        if (r1g < n)
            *(float2*)(T + (size_t)r1g * FD + col) =
                make_float2(dv1 * acc[t][2], dv1 * acc[t][3]);
    }
}

// ---------------------------------------------------------------------------
// Gather aggregation: one warp per node.
//   o = dinv[d] * ( sum_{s in N(d)} T[s] + 2*T[d] ) + b
// MODE 0: write bf16 hi/lo split (feeds next layer's MMA)
// MODE 1: write fp32 (final output)
// ---------------------------------------------------------------------------
template <int MODE>
__global__ void __launch_bounds__(256) k_agg(const float* __restrict__ T,
                                             const float* __restrict__ b,
                                             float* __restrict__ out, int n) {
    int node = blockIdx.x * (blockDim.x >> 5) + (threadIdx.x >> 5);
    if (node >= n) return;
    const int lane = threadIdx.x & 31;
    const int c = lane << 2;

    const int beg = g_rowptr[node];
    const int end = g_rowptr[node + 1];

    float4 self = *(const float4*)(T + (size_t)node * FD + c);
    float ax = 2.0f * self.x, ay = 2.0f * self.y;
    float az = 2.0f * self.z, aw = 2.0f * self.w;

    int j = beg;
    for (; j + 3 < end; j += 4) {
        int s0 = __ldg(g_csrc + j);
        int s1 = __ldg(g_csrc + j + 1);
        int s2 = __ldg(g_csrc + j + 2);
        int s3 = __ldg(g_csrc + j + 3);
        float4 v0 = *(const float4*)(T + (size_t)s0 * FD + c);
        float4 v1 = *(const float4*)(T + (size_t)s1 * FD + c);
        float4 v2 = *(const float4*)(T + (size_t)s2 * FD + c);
        float4 v3 = *(const float4*)(T + (size_t)s3 * FD + c);
        ax += v0.x + v1.x + v2.x + v3.x;
        ay += v0.y + v1.y + v2.y + v3.y;
        az += v0.z + v1.z + v2.z + v3.z;
        aw += v0.w + v1.w + v2.w + v3.w;
    }
    for (; j < end; j++) {
        int s = __ldg(g_csrc + j);
        float4 v = *(const float4*)(T + (size_t)s * FD + c);
        ax += v.x; ay += v.y; az += v.z; aw += v.w;
    }

    float dv = g_dinv[node];
    float4 bb = *(const float4*)(b + c);
    float4 o = make_float4(fmaf(dv, ax, bb.x), fmaf(dv, ay, bb.y),
                           fmaf(dv, az, bb.z), fmaf(dv, aw, bb.w));

    if (MODE == 1) {
        *(float4*)(out + (size_t)node * FD + c) = o;
    } else {
        uint2 hi, lo;
        split4(o, hi, lo);
        *(uint2*)(g_hh + (size_t)node * FD + c) = hi;
        *(uint2*)(g_hl + (size_t)node * FD + c) = lo;
    }
}

// ---------------------------------------------------------------------------
// Launcher
// ---------------------------------------------------------------------------
extern "C" void kernel_launch(void* const* d_in, const int* in_sizes, int n_in,
                              void* d_out, int out_size) {
    const float* x  = (const float*)d_in[0];
    const int*   ei = (const int*)  d_in[1];
    const float* W1 = (const float*)d_in[2];
    const float* b1 = (const float*)d_in[3];
    const float* W2 = (const float*)d_in[4];
    const float* b2 = (const float*)d_in[5];
    float* out = (float*)d_out;

    const int n = in_sizes[0] / FD;
    const int e = in_sizes[1] / 2;
    const int* src = ei;
    const int* dst = ei + e;

    float* bufT;
    __nv_bfloat16 *hh, *hl, *w1h, *w1l, *w2h, *w2l;
    cudaGetSymbolAddress((void**)&bufT, g_bufT);
    cudaGetSymbolAddress((void**)&hh,  g_hh);
    cudaGetSymbolAddress((void**)&hl,  g_hl);
    cudaGetSymbolAddress((void**)&w1h, g_W1h);
    cudaGetSymbolAddress((void**)&w1l, g_W1l);
    cudaGetSymbolAddress((void**)&w2h, g_W2h);
    cudaGetSymbolAddress((void**)&w2l, g_W2l);

    cudaFuncSetAttribute(k_gemm_mma, cudaFuncAttributeMaxDynamicSharedMemorySize,
                         SM_TOTAL);

    const int nb = (n + CHUNK - 1) / CHUNK;
    const int ngb = (n + TILE_M - 1) / TILE_M;

    // degree + normalization + CSR build
    k_cnt_init <<<(n + 255) / 256, 256>>>(n);
    k_deg_count<<<(e + 255) / 256, 256>>>(dst, e);
    k_dinv     <<<(n + 255) / 256, 256>>>(n);
    k_scan1    <<<nb, 256>>>(n);
    k_scan2    <<<1, 256>>>(nb, n);
    k_scan3    <<<nb, 256>>>(n);
    k_scatter  <<<(e + 255) / 256, 256>>>(src, dst, e);

    // weight + input splits
    k_wsplit  <<<(FD * FD + 255) / 256, 256>>>(W1, w1h, w1l);
    k_wsplit  <<<(FD * FD + 255) / 256, 256>>>(W2, w2h, w2l);
    k_split_x <<<(n * (FD / 4) + 255) / 256, 256>>>(x, n * (FD / 4));

    // layer 1
    k_gemm_mma<<<ngb, 256, SM_TOTAL>>>(hh, hl, w1h, w1l, bufT, n);
    k_agg<0>  <<<(n + 7) / 8, 256>>>(bufT, b1, nullptr, n);
    // layers 2-4
    for (int L = 0; L < 3; L++) {
        k_gemm_mma<<<ngb, 256, SM_TOTAL>>>(hh, hl, w2h, w2l, bufT, n);
        k_agg<0>  <<<(n + 7) / 8, 256>>>(bufT, b2, nullptr, n);
    }
    // layer 5 (final, fp32 output)
    k_gemm_mma<<<ngb, 256, SM_TOTAL>>>(hh, hl, w2h, w2l, bufT, n);
    k_agg<1>  <<<(n + 7) / 8, 256>>>(bufT, b2, out, n);
}

// round 7
// speedup vs baseline: 2.6923x; 1.0028x over previous
#include <cuda_runtime.h>
#include <cuda_bf16.h>
#include <stdint.h>

#define FD   128        // feature dim
#define MAXN 100000     // nodes
#define MAXE 1664000    // edges (1.6M + slack)
#define CHUNK 1024      // elements per scan block
#define TILE_M 128
#define SROW 136        // smem tile row stride in bf16 elems (272B, conflict-free)
#define SROWB (SROW * 2)

// ---------------------------------------------------------------------------
// Scratch (device globals — no allocation allowed in kernel_launch)
// ---------------------------------------------------------------------------
__device__ float g_dinv[MAXN];
__device__ int   g_cnt  [MAXN];
__device__ int   g_rowptr[MAXN + 1];
__device__ int   g_fill [MAXN];
__device__ int   g_csrc [MAXE];
__device__ int   g_bsum [256];
__device__ int   g_boff [256];
__device__ __align__(128) float g_bufT[(size_t)(MAXN + 128) * FD];
__device__ __align__(128) __nv_bfloat16 g_hh[(size_t)(MAXN + 128) * FD];
__device__ __align__(128) __nv_bfloat16 g_hl[(size_t)(MAXN + 128) * FD];
__device__ __align__(128) __nv_bfloat16 g_W1h[FD * FD];
__device__ __align__(128) __nv_bfloat16 g_W1l[FD * FD];
__device__ __align__(128) __nv_bfloat16 g_W2h[FD * FD];
__device__ __align__(128) __nv_bfloat16 g_W2l[FD * FD];

// ---------------------------------------------------------------------------
// Degree / normalization
// ---------------------------------------------------------------------------
__global__ void k_cnt_init(int n) {
    int i = blockIdx.x * blockDim.x + threadIdx.x;
    if (i < n) g_cnt[i] = 0;
}

__global__ void k_deg_count(const int* __restrict__ dst, int e) {
    int i = blockIdx.x * blockDim.x + threadIdx.x;
    if (i < e) atomicAdd(&g_cnt[dst[i]], 1);
}

__global__ void k_dinv(int n) {
    int i = blockIdx.x * blockDim.x + threadIdx.x;
    if (i < n) g_dinv[i] = rsqrtf(2.0f + (float)g_cnt[i]);
}

// ---------------------------------------------------------------------------
// 3-pass parallel exclusive scan of g_cnt -> g_rowptr / g_fill
// ---------------------------------------------------------------------------
__global__ void __launch_bounds__(256) k_scan1(int n) {
    const int t = threadIdx.x;
    const int base = blockIdx.x * CHUNK + t * 4;
    int s = 0;
#pragma unroll
    for (int m = 0; m < 4; m++) {
        int i = base + m;
        if (i < n) s += g_cnt[i];
    }
#pragma unroll
    for (int o = 16; o > 0; o >>= 1) s += __shfl_down_sync(0xffffffffu, s, o);
    __shared__ int ws[8];
    if ((t & 31) == 0) ws[t >> 5] = s;
    __syncthreads();
    if (t < 8) {
        int v = ws[t];
#pragma unroll
        for (int o = 4; o > 0; o >>= 1) v += __shfl_down_sync(0xffu, v, o);
        if (t == 0) g_bsum[blockIdx.x] = v;
    }
}

__global__ void __launch_bounds__(256) k_scan2(int nb, int n) {
    __shared__ int sh[256];
    int t = threadIdx.x;
    int v = (t < nb) ? g_bsum[t] : 0;
    sh[t] = v;
    __syncthreads();
#pragma unroll
    for (int o = 1; o < 256; o <<= 1) {
        int u = (t >= o) ? sh[t - o] : 0;
        __syncthreads();
        sh[t] += u;
        __syncthreads();
    }
    g_boff[t] = sh[t] - v;
    if (t == nb - 1) g_rowptr[n] = sh[t];
}

__global__ void __launch_bounds__(256) k_scan3(int n) {
    const int t = threadIdx.x;
    const int lane = t & 31;
    const int warp = t >> 5;
    const int base = blockIdx.x * CHUNK + t * 4;

    int c[4];
    int s = 0;
#pragma unroll
    for (int m = 0; m < 4; m++) {
        int i = base + m;
        c[m] = (i < n) ? g_cnt[i] : 0;
        s += c[m];
    }
    int incl = s;
#pragma unroll
    for (int o = 1; o < 32; o <<= 1) {
        int u = __shfl_up_sync(0xffffffffu, incl, o);
        if (lane >= o) incl += u;
    }
    __shared__ int wtot[8];
    if (lane == 31) wtot[warp] = incl;
    __syncthreads();
    int woff = 0;
#pragma unroll
    for (int w = 0; w < 7; w++)
        if (w < warp) woff += wtot[w];
    int pre = g_boff[blockIdx.x] + woff + incl - s;
#pragma unroll
    for (int m = 0; m < 4; m++) {
        int i = base + m;
        if (i < n) {
            g_rowptr[i] = pre;
            g_fill[i]   = pre;
            pre += c[m];
        }
    }
}

__global__ void k_scatter(const int* __restrict__ src, const int* __restrict__ dst, int e) {
    int i = blockIdx.x * blockDim.x + threadIdx.x;
    if (i < e) {
        int d = dst[i];
        int pos = atomicAdd(&g_fill[d], 1);
        g_csrc[pos] = src[i];
    }
}

// ---------------------------------------------------------------------------
// Split helpers: fp32 -> bf16 hi/lo
// ---------------------------------------------------------------------------
__device__ __forceinline__ void split4(float4 v, uint2& hi, uint2& lo) {
    __nv_bfloat16 hx = __float2bfloat16_rn(v.x);
    __nv_bfloat16 hy = __float2bfloat16_rn(v.y);
    __nv_bfloat16 hz = __float2bfloat16_rn(v.z);
    __nv_bfloat16 hw = __float2bfloat16_rn(v.w);
    __nv_bfloat16 lx = __float2bfloat16_rn(v.x - __bfloat162float(hx));
    __nv_bfloat16 ly = __float2bfloat16_rn(v.y - __bfloat162float(hy));
    __nv_bfloat16 lz = __float2bfloat16_rn(v.z - __bfloat162float(hz));
    __nv_bfloat16 lw = __float2bfloat16_rn(v.w - __bfloat162float(hw));
    __nv_bfloat162 h0 = __halves2bfloat162(hx, hy), h1 = __halves2bfloat162(hz, hw);
    __nv_bfloat162 l0 = __halves2bfloat162(lx, ly), l1 = __halves2bfloat162(lz, lw);
    hi = make_uint2(*(uint32_t*)&h0, *(uint32_t*)&h1);
    lo = make_uint2(*(uint32_t*)&l0, *(uint32_t*)&l1);
}

__global__ void __launch_bounds__(256) k_split_x(const float* __restrict__ x, int total4) {
    int i = blockIdx.x * blockDim.x + threadIdx.x;   // float4 index
    if (i >= total4) return;
    float4 v = *(const float4*)(x + (size_t)i * 4);
    uint2 hi, lo;
    split4(v, hi, lo);
    *(uint2*)(g_hh + (size_t)i * 4) = hi;
    *(uint2*)(g_hl + (size_t)i * 4) = lo;
}

// W[k][n] fp32 -> Wh/Wl[n][k] bf16 (transposed: n rows, k contiguous)
__global__ void __launch_bounds__(256) k_wsplit(const float* __restrict__ W,
                                                __nv_bfloat16* __restrict__ Wh,
                                                __nv_bfloat16* __restrict__ Wl) {
    int i = blockIdx.x * blockDim.x + threadIdx.x;   // i = n*128 + k
    if (i >= FD * FD) return;
    int nn = i >> 7, kk = i & 127;
    float w = W[kk * FD + nn];
    __nv_bfloat16 h = __float2bfloat16_rn(w);
    __nv_bfloat16 l = __float2bfloat16_rn(w - __bfloat162float(h));
    Wh[i] = h;
    Wl[i] = l;
}

// ---------------------------------------------------------------------------
// HMMA GEMM: T[n,128] = dinv[row] * (A @ W), fp32 via bf16 3-term split
//   D = Ah@Wh + Ah@Wl + Al@Wh   (fp32 accumulation in registers)
// 256 threads, 128x128 tile, mma.sync.m16n8k16.bf16.
// A fragments register-resident per term; B loaded with ldmatrix.x4
// (one x4 = fragments for TWO n-tiles) -> LDSM count halved vs x2 scheme.
// ---------------------------------------------------------------------------
__device__ __forceinline__ uint32_t smem_to_u32(const void* p) {
    uint32_t a;
    asm("{ .reg .u64 t; cvta.to.shared.u64 t, %1; cvt.u32.u64 %0, t; }"
        : "=r"(a) : "l"(p));
    return a;
}

__device__ __forceinline__ void ldsm_x4(uint32_t& r0, uint32_t& r1,
                                        uint32_t& r2, uint32_t& r3, uint32_t addr) {
    asm volatile("ldmatrix.sync.aligned.m8n8.x4.shared.b16 {%0,%1,%2,%3}, [%4];"
                 : "=r"(r0), "=r"(r1), "=r"(r2), "=r"(r3) : "r"(addr));
}

__device__ __forceinline__ void mma16816(float* c, uint32_t a0, uint32_t a1,
                                         uint32_t a2, uint32_t a3,
                                         uint32_t b0, uint32_t b1) {
    asm volatile(
        "mma.sync.aligned.m16n8k16.row.col.f32.bf16.bf16.f32 "
        "{%0,%1,%2,%3}, {%4,%5,%6,%7}, {%8,%9}, {%0,%1,%2,%3};"
        : "+f"(c[0]), "+f"(c[1]), "+f"(c[2]), "+f"(c[3])
        : "r"(a0), "r"(a1), "r"(a2), "r"(a3), "r"(b0), "r"(b1));
}

// Copy a 128x128 bf16 tile (row-major, contiguous) to smem with SROW stride.
__device__ __forceinline__ void load_tile(char* dst, const __nv_bfloat16* g,
                                          int valid_rows) {
    const uint4* gp = (const uint4*)g;   // 2048 uint4, 16 per row
    const int tid = threadIdx.x;
#pragma unroll
    for (int i = 0; i < 8; i++) {
        int gi = tid + i * 256;
        int r  = gi >> 4;
        int ch = gi & 15;
        uint4 v = (r < valid_rows) ? gp[gi] : make_uint4(0u, 0u, 0u, 0u);
        *(uint4*)(dst + r * SROWB + ch * 16) = v;
    }
}

#define SM_AH 0
#define SM_AL (128 * SROWB)
#define SM_WH (2 * 128 * SROWB)
#define SM_WL (3 * 128 * SROWB)
#define SM_TOTAL (4 * 128 * SROWB)

__global__ void __launch_bounds__(256)
k_gemm_mma(const __nv_bfloat16* __restrict__ Ah,
           const __nv_bfloat16* __restrict__ Al,
           const __nv_bfloat16* __restrict__ Wh,
           const __nv_bfloat16* __restrict__ Wl,
           float* __restrict__ T, int n) {
    extern __shared__ char smem[];
    const int tid  = threadIdx.x;
    const int lane = tid & 31;
    const int wr0  = (tid >> 5) << 4;    // warp row offset: 0..112
    const int row0 = blockIdx.x * TILE_M;
    const int valid = min(TILE_M, n - row0);

    load_tile(smem + SM_AH, Ah + (size_t)row0 * FD, valid);
    load_tile(smem + SM_AL, Al + (size_t)row0 * FD, valid);
    load_tile(smem + SM_WH, Wh, 128);
    load_tile(smem + SM_WL, Wl, 128);
    __syncthreads();

    const uint32_t sb = smem_to_u32(smem);
    // A frag address: row = wr0 + (lane&15), +16B for lanes 16-31
    const uint32_t aoff = sb + (uint32_t)(wr0 + (lane & 15)) * SROWB
                        + (uint32_t)((lane >> 4) << 4);
    // B x4 address: lane group g = lane>>3 (0..3):
    //   n-row = (g>>1)*8 + (lane&7),  k byte offset = (g&1)*16
    // -> matrices: {n0-7,k0-7},{n0-7,k8-15},{n8-15,k0-7},{n8-15,k8-15}
    const uint32_t boff = sb + (uint32_t)(((lane >> 4) << 3) + (lane & 7)) * SROWB
                        + (uint32_t)(((lane >> 3) & 1) << 4);

    float acc[16][4];
#pragma unroll
    for (int t = 0; t < 16; t++)
#pragma unroll
        for (int j = 0; j < 4; j++) acc[t][j] = 0.0f;

#pragma unroll
    for (int term = 0; term < 3; term++) {
        const uint32_t aBase = aoff + ((term == 2) ? SM_AL : SM_AH);
        const uint32_t bBase = boff + ((term == 1) ? SM_WL : SM_WH);

        // load all A fragments for this term into registers (8 k-steps)
        uint32_t a[8][4];
#pragma unroll
        for (int ks = 0; ks < 8; ks++)
            ldsm_x4(a[ks][0], a[ks][1], a[ks][2], a[ks][3], aBase + ks * 32);

        // n-tile pairs outer, k inner
#pragma unroll
        for (int nt = 0; nt < 8; nt++) {
            const uint32_t bnt = bBase + (uint32_t)nt * 16 * SROWB;
#pragma unroll
            for (int ks = 0; ks < 8; ks++) {
                uint32_t b0, b1, b2, b3;
                ldsm_x4(b0, b1, b2, b3, bnt + ks * 32);
                mma16816(acc[nt * 2],     a[ks][0], a[ks][1], a[ks][2], a[ks][3], b0, b1);
                mma16816(acc[nt * 2 + 1], a[ks][0], a[ks][1], a[ks][2], a[ks][3], b2, b3);
            }
        }
    }

    // epilogue: scale by dinv[row], store fp32
    const int r0g = row0 + wr0 + (lane >> 2);
    const int r1g = r0g + 8;
    const float dv0 = (r0g < n) ? g_dinv[r0g] : 0.0f;
    const float dv1 = (r1g < n) ? g_dinv[r1g] : 0.0f;
    const int cbase = (lane & 3) << 1;
#pragma unroll
    for (int t = 0; t < 16; t++) {
        const int col = t * 8 + cbase;
        if (r0g < n)
            *(float2*)(T + (size_t)r0g * FD + col) =
                make_float2(dv0 * acc[t][0], dv0 * acc[t][1]);
        if (r1g < n)
            *(float2*)(T + (size_t)r1g * FD + col) =
                make_float2(dv1 * acc[t][2], dv1 * acc[t][3]);
    }
}

// ---------------------------------------------------------------------------
// Gather aggregation: one warp per node.
//   o = dinv[d] * ( sum_{s in N(d)} T[s] + 2*T[d] ) + b
// MODE 0: write bf16 hi/lo split (feeds next layer's MMA)
// MODE 1: write fp32 (final output)
// ---------------------------------------------------------------------------
template <int MODE>
__global__ void __launch_bounds__(256) k_agg(const float* __restrict__ T,
                                             const float* __restrict__ b,
                                             float* __restrict__ out, int n) {
    int node = blockIdx.x * (blockDim.x >> 5) + (threadIdx.x >> 5);
    if (node >= n) return;
    const int lane = threadIdx.x & 31;
    const int c = lane << 2;

    const int beg = g_rowptr[node];
    const int end = g_rowptr[node + 1];

    float4 self = *(const float4*)(T + (size_t)node * FD + c);
    float ax = 2.0f * self.x, ay = 2.0f * self.y;
    float az = 2.0f * self.z, aw = 2.0f * self.w;

    int j = beg;
    for (; j + 3 < end; j += 4) {
        int s0 = __ldg(g_csrc + j);
        int s1 = __ldg(g_csrc + j + 1);
        int s2 = __ldg(g_csrc + j + 2);
        int s3 = __ldg(g_csrc + j + 3);
        float4 v0 = *(const float4*)(T + (size_t)s0 * FD + c);
        float4 v1 = *(const float4*)(T + (size_t)s1 * FD + c);
        float4 v2 = *(const float4*)(T + (size_t)s2 * FD + c);
        float4 v3 = *(const float4*)(T + (size_t)s3 * FD + c);
        ax += v0.x + v1.x + v2.x + v3.x;
        ay += v0.y + v1.y + v2.y + v3.y;
        az += v0.z + v1.z + v2.z + v3.z;
        aw += v0.w + v1.w + v2.w + v3.w;
    }
    for (; j < end; j++) {
        int s = __ldg(g_csrc + j);
        float4 v = *(const float4*)(T + (size_t)s * FD + c);
        ax += v.x; ay += v.y; az += v.z; aw += v.w;
    }

    float dv = g_dinv[node];
    float4 bb = *(const float4*)(b + c);
    float4 o = make_float4(fmaf(dv, ax, bb.x), fmaf(dv, ay, bb.y),
                           fmaf(dv, az, bb.z), fmaf(dv, aw, bb.w));

    if (MODE == 1) {
        *(float4*)(out + (size_t)node * FD + c) = o;
    } else {
        uint2 hi, lo;
        split4(o, hi, lo);
        *(uint2*)(g_hh + (size_t)node * FD + c) = hi;
        *(uint2*)(g_hl + (size_t)node * FD + c) = lo;
    }
}

// ---------------------------------------------------------------------------
// Launcher
// ---------------------------------------------------------------------------
extern "C" void kernel_launch(void* const* d_in, const int* in_sizes, int n_in,
                              void* d_out, int out_size) {
    const float* x  = (const float*)d_in[0];
    const int*   ei = (const int*)  d_in[1];
    const float* W1 = (const float*)d_in[2];
    const float* b1 = (const float*)d_in[3];
    const float* W2 = (const float*)d_in[4];
    const float* b2 = (const float*)d_in[5];
    float* out = (float*)d_out;

    const int n = in_sizes[0] / FD;
    const int e = in_sizes[1] / 2;
    const int* src = ei;
    const int* dst = ei + e;

    float* bufT;
    __nv_bfloat16 *hh, *hl, *w1h, *w1l, *w2h, *w2l;
    cudaGetSymbolAddress((void**)&bufT, g_bufT);
    cudaGetSymbolAddress((void**)&hh,  g_hh);
    cudaGetSymbolAddress((void**)&hl,  g_hl);
    cudaGetSymbolAddress((void**)&w1h, g_W1h);
    cudaGetSymbolAddress((void**)&w1l, g_W1l);
    cudaGetSymbolAddress((void**)&w2h, g_W2h);
    cudaGetSymbolAddress((void**)&w2l, g_W2l);

    cudaFuncSetAttribute(k_gemm_mma, cudaFuncAttributeMaxDynamicSharedMemorySize,
                         SM_TOTAL);

    const int nb = (n + CHUNK - 1) / CHUNK;
    const int ngb = (n + TILE_M - 1) / TILE_M;

    // degree + normalization + CSR build
    k_cnt_init <<<(n + 255) / 256, 256>>>(n);
    k_deg_count<<<(e + 255) / 256, 256>>>(dst, e);
    k_dinv     <<<(n + 255) / 256, 256>>>(n);
    k_scan1    <<<nb, 256>>>(n);
    k_scan2    <<<1, 256>>>(nb, n);
    k_scan3    <<<nb, 256>>>(n);
    k_scatter  <<<(e + 255) / 256, 256>>>(src, dst, e);

    // weight + input splits
    k_wsplit  <<<(FD * FD + 255) / 256, 256>>>(W1, w1h, w1l);
    k_wsplit  <<<(FD * FD + 255) / 256, 256>>>(W2, w2h, w2l);
    k_split_x <<<(n * (FD / 4) + 255) / 256, 256>>>(x, n * (FD / 4));

    // layer 1
    k_gemm_mma<<<ngb, 256, SM_TOTAL>>>(hh, hl, w1h, w1l, bufT, n);
    k_agg<0>  <<<(n + 7) / 8, 256>>>(bufT, b1, nullptr, n);
    // layers 2-4
    for (int L = 0; L < 3; L++) {
        k_gemm_mma<<<ngb, 256, SM_TOTAL>>>(hh, hl, w2h, w2l, bufT, n);
        k_agg<0>  <<<(n + 7) / 8, 256>>>(bufT, b2, nullptr, n);
    }
    // layer 5 (final, fp32 output)
    k_gemm_mma<<<ngb, 256, SM_TOTAL>>>(hh, hl, w2h, w2l, bufT, n);
    k_agg<1>  <<<(n + 7) / 8, 256>>>(bufT, b2, out, n);
}